// round 10
// baseline (speedup 1.0000x reference)
#include <cuda_runtime.h>
#include <cuda_fp16.h>
#include <cstdint>
#include <cstddef>

#define KT 8192
#define KE 8
#define KH 2048
#define KI 5632

// ---------- device scratch (static, no allocs) ----------
__device__ __align__(256) __half g_X [(size_t)KT*KH];
__device__ __align__(256) __half g_W1[(size_t)KE*KI*KH];
__device__ __align__(256) __half g_W3[(size_t)KE*KI*KH];
__device__ __align__(256) __half g_W2[(size_t)KE*KH*KI];
__device__ __align__(256) __half g_Hb[(size_t)KE*KT*KI];
__device__ int   g_cnt[KE];
__device__ int   g_tok[KE*KT];
__device__ float g_tw [KE*KT];

// ---------- helpers ----------
__device__ __forceinline__ uint32_t smem_u32(const void* p){
    return (uint32_t)__cvta_generic_to_shared(p);
}
__device__ __forceinline__ void cp16(uint32_t dst, const void* src){
    asm volatile("cp.async.cg.shared.global [%0], [%1], 16;" :: "r"(dst), "l"(src));
}
__device__ __forceinline__ void cp_commit(){ asm volatile("cp.async.commit_group;"); }
template<int N> __device__ __forceinline__ void cp_wait(){
    asm volatile("cp.async.wait_group %0;" :: "n"(N));
}
__device__ __forceinline__ void ldsm4(uint32_t* r, uint32_t a){
    asm volatile("ldmatrix.sync.aligned.m8n8.x4.shared.b16 {%0,%1,%2,%3}, [%4];"
                 : "=r"(r[0]),"=r"(r[1]),"=r"(r[2]),"=r"(r[3]) : "r"(a));
}
__device__ __forceinline__ void mma16(float* d, const uint32_t* a, uint32_t b0, uint32_t b1){
    asm volatile("mma.sync.aligned.m16n8k16.row.col.f32.f16.f16.f32 "
                 "{%0,%1,%2,%3}, {%4,%5,%6,%7}, {%8,%9}, {%0,%1,%2,%3};"
                 : "+f"(d[0]),"+f"(d[1]),"+f"(d[2]),"+f"(d[3])
                 : "r"(a[0]),"r"(a[1]),"r"(a[2]),"r"(a[3]),"r"(b0),"r"(b1));
}

// ---------- zero output ----------
__global__ void k_zero(float4* out){
    int i = blockIdx.x*blockDim.x + threadIdx.x;
    const int n4 = KT*KH/4;
    float4 z = make_float4(0.f,0.f,0.f,0.f);
    for(int j=i;j<n4;j+=gridDim.x*blockDim.x) out[j]=z;
}

// ---------- routing: top-2 + softmax + compaction ----------
__global__ void k_route(const float* __restrict__ lg){
    int t = blockIdx.x*blockDim.x + threadIdx.x;
    if(t>=KT) return;
    float v[KE];
    #pragma unroll
    for(int e=0;e<KE;e++) v[e]=lg[t*KE+e];
    int i0=0;
    #pragma unroll
    for(int e=1;e<KE;e++) if(v[e]>v[i0]) i0=e;
    int i1=-1;
    #pragma unroll
    for(int e=0;e<KE;e++){ if(e==i0) continue; if(i1<0 || v[e]>v[i1]) i1=e; }
    float wa = 1.f/(1.f + __expf(v[i1]-v[i0]));
    float wb = 1.f - wa;
    int s0 = atomicAdd(&g_cnt[i0],1);
    g_tok[i0*KT+s0]=t; g_tw[i0*KT+s0]=wa;
    int s1 = atomicAdd(&g_cnt[i1],1);
    g_tok[i1*KT+s1]=t; g_tw[i1*KT+s1]=wb;
}

// ---------- fp32 -> fp16 conversions ----------
__global__ void k_cvtx(const float4* __restrict__ s){
    if(blockIdx.x==0 && threadIdx.x<KE) g_cnt[threadIdx.x]=0;  // reset counts for k_route
    __half2* d = (__half2*)g_X;
    int i = blockIdx.x*blockDim.x + threadIdx.x;
    const int n4 = KT*KH/4;
    for(int j=i;j<n4;j+=gridDim.x*blockDim.x){
        float4 a = s[j];
        d[2*j  ] = __floats2half2_rn(a.x,a.y);
        d[2*j+1] = __floats2half2_rn(a.z,a.w);
    }
}
__global__ void k_cvtw13(const float4* __restrict__ s1, const float4* __restrict__ s3){
    __half2* d1 = (__half2*)g_W1;
    __half2* d3 = (__half2*)g_W3;
    int i = blockIdx.x*blockDim.x + threadIdx.x;
    const int n4 = KE*KI*KH/4;
    for(int j=i;j<n4;j+=gridDim.x*blockDim.x){
        float4 a = s1[j];
        d1[2*j  ] = __floats2half2_rn(a.x,a.y);
        d1[2*j+1] = __floats2half2_rn(a.z,a.w);
        float4 b = s3[j];
        d3[2*j  ] = __floats2half2_rn(b.x,b.y);
        d3[2*j+1] = __floats2half2_rn(b.z,b.w);
    }
}
__global__ void k_cvtw2(const float4* __restrict__ s){
    __half2* d = (__half2*)g_W2;
    int i = blockIdx.x*blockDim.x + threadIdx.x;
    const int n4 = KE*KH*KI/4;
    for(int j=i;j<n4;j+=gridDim.x*blockDim.x){
        float4 a = s[j];
        d[2*j  ] = __floats2half2_rn(a.x,a.y);
        d[2*j+1] = __floats2half2_rn(a.z,a.w);
    }
}

// ---------- GEMM: PHASE 0 = gate/up (silu*up*tw -> g_Hb fp16), N=64 x {W1,W3}
//                  PHASE 1 = down-proj (atomicAdd -> out), N=128 x W2
// CTA tile 128(M) x 128(B-rows) x 64(K); 8 warps, 3-stage cp.async,
// next-stage loads interleaved INTO the km loop (spread LDGSTS issue)
template<int PHASE>
__global__ void __launch_bounds__(256,2) k_gemm(float* __restrict__ out){
    constexpr int KD = (PHASE==0) ? KH : KI;   // GEMM K dim
    constexpr int NB = (PHASE==0) ? 2  : 1;    // number of B matrices
    constexpr int NI = (PHASE==0) ? 4  : 8;    // n-frags (8 cols) per warp per matrix
    constexpr int NT = (PHASE==0) ? 64 : 128;  // N cols per matrix per CTA
    constexpr int KS = KD/64;
    constexpr int AST = 128*64;                // halves per A stage
    constexpr int BST = 128*64;                // halves per B stage (128 rows total)

    const int e  = blockIdx.z;
    const int cnt = g_cnt[e];
    const int m0 = blockIdx.x*128;             // m fastest-varying
    if(m0 >= cnt) return;
    const int n0 = blockIdx.y*NT;

    extern __shared__ __half sm[];
    __half* sA = sm;              // [3][128][64]
    __half* sW = sm + 3*AST;      // [3][128][64]
    __shared__ int   s_tok[128];
    __shared__ float s_tw [128];

    const int tid = threadIdx.x;
    if(tid < 128){
        int r = min(m0+tid, cnt-1);
        s_tok[tid] = g_tok[e*KT + r];
        if(PHASE==0) s_tw[tid] = g_tw[e*KT + r];
    }
    __syncthreads();

    const __half* Wp0 = (PHASE==0) ? (g_W1 + (size_t)e*KI*KH) : (g_W2 + (size_t)e*KH*KI);
    const __half* Wp1 = g_W3 + (size_t)e*KI*KH;

    // half = 0/1: issue 2 of the 4 per-thread A (or B) cp.async chunks
    auto loadA2 = [&](int L, int half){
        const int st = L%3, k0 = L*64;
        uint32_t baseA = smem_u32(sA + st*AST);
        #pragma unroll
        for(int it=half*2; it<half*2+2; it++){
            int c = it*256 + tid;
            int row = c>>3, cb = c&7;
            int sc = cb ^ (row&7);
            const __half* src = (PHASE==0)
                ? (g_X  + (size_t)s_tok[row]*KH + k0 + cb*8)
                : (g_Hb + (size_t)(e*KT + m0 + row)*KI + k0 + cb*8);
            cp16(baseA + row*128 + sc*16, src);
        }
    };
    auto loadW2 = [&](int L, int half){
        const int st = L%3, k0 = L*64;
        uint32_t baseW = smem_u32(sW + st*BST);
        #pragma unroll
        for(int it=half*2; it<half*2+2; it++){
            int c = it*256 + tid;
            int row = c>>3, cb = c&7;
            int sc = cb ^ (row&7);
            const __half* W = (PHASE==0 && row>=64) ? Wp1 : Wp0;
            int wrow = (PHASE==0) ? (row&63) : row;
            cp16(baseW + row*128 + sc*16, W + (size_t)(n0+wrow)*KD + k0 + cb*8);
        }
    };
    auto load_stage = [&](int L){
        loadA2(L,0); loadA2(L,1); loadW2(L,0); loadW2(L,1); cp_commit();
    };

    float acc[NB][2][NI][4];
    #pragma unroll
    for(int b=0;b<NB;b++)
        #pragma unroll
        for(int mi=0;mi<2;mi++)
            #pragma unroll
            for(int ni=0;ni<NI;ni++)
                #pragma unroll
                for(int k=0;k<4;k++) acc[b][mi][ni][k]=0.f;

    const int lane = tid & 31, warp = tid >> 5;
    const int wm = (warp>>1)*32, wn = (warp&1)*(NI*8);

    // hoisted fragment addressing (row&7 == lane&7 for every fragment)
    uint32_t kx[4];
    #pragma unroll
    for(int km=0;km<4;km++) kx[km] = (uint32_t)(((km*2 + (lane>>4)) ^ (lane&7))*16);
    uint32_t aoff[2], boff[NB*NI/2];
    #pragma unroll
    for(int mi=0;mi<2;mi++) aoff[mi] = (uint32_t)((wm + mi*16 + (lane&15))*128);
    #pragma unroll
    for(int b=0;b<NB;b++)
        #pragma unroll
        for(int nb=0;nb<NI/2;nb++)
            boff[b*(NI/2)+nb] = (uint32_t)(b*64*128 + (wn + nb*16 + (lane&15))*128);

    auto compute_km = [&](uint32_t baseA, uint32_t baseW, int km){
        uint32_t a[2][4];
        #pragma unroll
        for(int mi=0;mi<2;mi++)
            ldsm4(a[mi], baseA + aoff[mi] + kx[km]);
        #pragma unroll
        for(int b=0;b<NB;b++){
            uint32_t bf[NI][2];
            #pragma unroll
            for(int nb=0;nb<NI/2;nb++){
                uint32_t r[4];
                ldsm4(r, baseW + boff[b*(NI/2)+nb] + kx[km]);
                bf[nb*2  ][0]=r[0]; bf[nb*2+1][0]=r[1];
                bf[nb*2  ][1]=r[2]; bf[nb*2+1][1]=r[3];
            }
            #pragma unroll
            for(int mi=0;mi<2;mi++)
                #pragma unroll
                for(int ni=0;ni<NI;ni++)
                    mma16(acc[b][mi][ni], a[mi], bf[ni][0], bf[ni][1]);
        }
    };

    load_stage(0); load_stage(1);
    for(int ks=0; ks<KS; ks++){
        if(ks+1<KS) cp_wait<1>(); else cp_wait<0>();
        __syncthreads();
        const int st = ks%3;
        uint32_t baseA = smem_u32(sA + st*AST);
        uint32_t baseW = smem_u32(sW + st*BST);
        const int L = ks+2;
        const bool ld = (L<KS);
        // km loop with next-stage loads interleaved AFTER each km's LDSM+HMMA
        compute_km(baseA, baseW, 0);
        if(ld) loadA2(L,0);
        compute_km(baseA, baseW, 1);
        if(ld) loadA2(L,1);
        compute_km(baseA, baseW, 2);
        if(ld) loadW2(L,0);
        compute_km(baseA, baseW, 3);
        if(ld){ loadW2(L,1); cp_commit(); }
    }

    // epilogue
    #pragma unroll
    for(int mi=0;mi<2;mi++){
        #pragma unroll
        for(int hh=0;hh<2;hh++){
            int row = wm + mi*16 + (lane>>2) + hh*8;
            int r   = m0 + row;
            if(PHASE==0){
                float tw = (r < cnt) ? s_tw[row] : 0.f;
                __half* dst = g_Hb + (size_t)(e*KT + r)*KI + n0;
                #pragma unroll
                for(int ni=0;ni<NI;ni++){
                    int col = wn + ni*8 + (lane&3)*2;
                    float gg0 = acc[0][mi][ni][hh*2], gg1 = acc[0][mi][ni][hh*2+1];
                    float uu0 = acc[NB-1][mi][ni][hh*2], uu1 = acc[NB-1][mi][ni][hh*2+1];
                    float h0 = tw * (gg0/(1.f+__expf(-gg0))) * uu0;
                    float h1 = tw * (gg1/(1.f+__expf(-gg1))) * uu1;
                    *(__half2*)(dst + col) = __floats2half2_rn(h0,h1);
                }
            } else {
                if(r < cnt){
                    int t = s_tok[row];
                    float* dst = out + (size_t)t*KH + n0;
                    #pragma unroll
                    for(int ni=0;ni<NI;ni++){
                        int col = wn + ni*8 + (lane&3)*2;
                        atomicAdd(dst + col    , acc[0][mi][ni][hh*2  ]);
                        atomicAdd(dst + col + 1, acc[0][mi][ni][hh*2+1]);
                    }
                }
            }
        }
    }
}

// ---------- launch ----------
extern "C" void kernel_launch(void* const* d_in, const int* in_sizes, int n_in,
                              void* d_out, int out_size){
    const float* hs = (const float*)d_in[0];
    const float* lg = (const float*)d_in[1];
    const float* w1 = (const float*)d_in[2];
    const float* w2 = (const float*)d_in[3];
    const float* w3 = (const float*)d_in[4];
    float* out = (float*)d_out;

    const int DS = 3*(128*64 + 128*64)*2;  // 98304 B (both phases)
    cudaFuncSetAttribute(k_gemm<0>, cudaFuncAttributeMaxDynamicSharedMemorySize, DS);
    cudaFuncSetAttribute(k_gemm<1>, cudaFuncAttributeMaxDynamicSharedMemorySize, DS);

    // keep k_gemm<0> at launch #4 (ncu profile target)
    k_cvtx  <<<2048, 256>>>((const float4*)hs);                      // 1 (also zeroes g_cnt)
    k_route <<<KT/256, 256>>>(lg);                                   // 2
    k_cvtw13<<<4096, 256>>>((const float4*)w1, (const float4*)w3);   // 3

    dim3 gA(KT/128, KI/64, KE);   // m fastest
    k_gemm<0><<<gA, 256, DS>>>(out);                                 // 4  <- profile target

    k_cvtw2 <<<4096, 256>>>((const float4*)w2);                      // 5
    k_zero  <<<512, 256>>>((float4*)out);                            // 6

    dim3 gB(KT/128, KH/128, KE);  // m fastest
    k_gemm<1><<<gB, 256, DS>>>(out);                                 // 7
}

// round 12
// speedup vs baseline: 1.0113x; 1.0113x over previous
#include <cuda_runtime.h>
#include <cuda_fp16.h>
#include <cstdint>
#include <cstddef>

#define KT 8192
#define KE 8
#define KH 2048
#define KI 5632

// ---------- device scratch (static, no allocs) ----------
__device__ __align__(256) __half g_X [(size_t)KT*KH];
__device__ __align__(256) __half g_W1[(size_t)KE*KI*KH];
__device__ __align__(256) __half g_W3[(size_t)KE*KI*KH];
__device__ __align__(256) __half g_W2[(size_t)KE*KH*KI];
__device__ __align__(256) __half g_Hb[(size_t)KE*KT*KI];
__device__ int   g_cnt[KE];
__device__ int   g_tok[KE*KT];
__device__ float g_tw [KE*KT];

// ---------- helpers ----------
__device__ __forceinline__ uint32_t smem_u32(const void* p){
    return (uint32_t)__cvta_generic_to_shared(p);
}
__device__ __forceinline__ void cp16(uint32_t dst, const void* src){
    asm volatile("cp.async.cg.shared.global [%0], [%1], 16;" :: "r"(dst), "l"(src));
}
// .noinc: arrival consumes one unit of the pre-initialized expected count
// (default variant self-increments and would deadlock a count=N barrier)
__device__ __forceinline__ void cp_mbar_arrive(uint32_t mb){
    asm volatile("cp.async.mbarrier.arrive.noinc.shared.b64 [%0];" :: "r"(mb) : "memory");
}
__device__ __forceinline__ void mbar_init(uint32_t a, uint32_t c){
    asm volatile("mbarrier.init.shared.b64 [%0], %1;"::"r"(a),"r"(c):"memory");
}
__device__ __forceinline__ void mbar_arrive(uint32_t a){
    asm volatile("mbarrier.arrive.shared.b64 _, [%0];"::"r"(a):"memory");
}
__device__ __forceinline__ void mbar_wait(uint32_t a, uint32_t ph){
    asm volatile("{\n\t.reg .pred P;\n\tWL%=:\n\t"
                 "mbarrier.try_wait.parity.shared.b64 P, [%0], %1;\n\t"
                 "@!P bra WL%=;\n\t}"::"r"(a),"r"(ph):"memory");
}
__device__ __forceinline__ void ldsm4(uint32_t* r, uint32_t a){
    asm volatile("ldmatrix.sync.aligned.m8n8.x4.shared.b16 {%0,%1,%2,%3}, [%4];"
                 : "=r"(r[0]),"=r"(r[1]),"=r"(r[2]),"=r"(r[3]) : "r"(a));
}
__device__ __forceinline__ void mma16(float* d, const uint32_t* a, uint32_t b0, uint32_t b1){
    asm volatile("mma.sync.aligned.m16n8k16.row.col.f32.f16.f16.f32 "
                 "{%0,%1,%2,%3}, {%4,%5,%6,%7}, {%8,%9}, {%0,%1,%2,%3};"
                 : "+f"(d[0]),"+f"(d[1]),"+f"(d[2]),"+f"(d[3])
                 : "r"(a[0]),"r"(a[1]),"r"(a[2]),"r"(a[3]),"r"(b0),"r"(b1));
}

// ---------- zero output ----------
__global__ void k_zero(float4* out){
    int i = blockIdx.x*blockDim.x + threadIdx.x;
    const int n4 = KT*KH/4;
    float4 z = make_float4(0.f,0.f,0.f,0.f);
    for(int j=i;j<n4;j+=gridDim.x*blockDim.x) out[j]=z;
}

// ---------- routing: top-2 + softmax + compaction ----------
__global__ void k_route(const float* __restrict__ lg){
    int t = blockIdx.x*blockDim.x + threadIdx.x;
    if(t>=KT) return;
    float v[KE];
    #pragma unroll
    for(int e=0;e<KE;e++) v[e]=lg[t*KE+e];
    int i0=0;
    #pragma unroll
    for(int e=1;e<KE;e++) if(v[e]>v[i0]) i0=e;
    int i1=-1;
    #pragma unroll
    for(int e=0;e<KE;e++){ if(e==i0) continue; if(i1<0 || v[e]>v[i1]) i1=e; }
    float wa = 1.f/(1.f + __expf(v[i1]-v[i0]));
    float wb = 1.f - wa;
    int s0 = atomicAdd(&g_cnt[i0],1);
    g_tok[i0*KT+s0]=t; g_tw[i0*KT+s0]=wa;
    int s1 = atomicAdd(&g_cnt[i1],1);
    g_tok[i1*KT+s1]=t; g_tw[i1*KT+s1]=wb;
}

// ---------- fp32 -> fp16 conversions ----------
__global__ void k_cvtx(const float4* __restrict__ s){
    if(blockIdx.x==0 && threadIdx.x<KE) g_cnt[threadIdx.x]=0;  // reset counts for k_route
    __half2* d = (__half2*)g_X;
    int i = blockIdx.x*blockDim.x + threadIdx.x;
    const int n4 = KT*KH/4;
    for(int j=i;j<n4;j+=gridDim.x*blockDim.x){
        float4 a = s[j];
        d[2*j  ] = __floats2half2_rn(a.x,a.y);
        d[2*j+1] = __floats2half2_rn(a.z,a.w);
    }
}
__global__ void k_cvtw13(const float4* __restrict__ s1, const float4* __restrict__ s3){
    __half2* d1 = (__half2*)g_W1;
    __half2* d3 = (__half2*)g_W3;
    int i = blockIdx.x*blockDim.x + threadIdx.x;
    const int n4 = KE*KI*KH/4;
    for(int j=i;j<n4;j+=gridDim.x*blockDim.x){
        float4 a = s1[j];
        d1[2*j  ] = __floats2half2_rn(a.x,a.y);
        d1[2*j+1] = __floats2half2_rn(a.z,a.w);
        float4 b = s3[j];
        d3[2*j  ] = __floats2half2_rn(b.x,b.y);
        d3[2*j+1] = __floats2half2_rn(b.z,b.w);
    }
}
__global__ void k_cvtw2(const float4* __restrict__ s){
    __half2* d = (__half2*)g_W2;
    int i = blockIdx.x*blockDim.x + threadIdx.x;
    const int n4 = KE*KH*KI/4;
    for(int j=i;j<n4;j+=gridDim.x*blockDim.x){
        float4 a = s[j];
        d[2*j  ] = __floats2half2_rn(a.x,a.y);
        d[2*j+1] = __floats2half2_rn(a.z,a.w);
    }
}

// ---------- GEMM: PHASE 0 = gate/up (silu*up*tw -> g_Hb fp16), N=64 x {W1,W3}
//                  PHASE 1 = down-proj (atomicAdd -> out), N=128 x W2
// CTA tile 128(M) x 128(B-rows) x 64(K); 8 warps; 3-stage pipeline with
// mbarrier producer/consumer sync (no per-k-step __syncthreads convoy)
template<int PHASE>
__global__ void __launch_bounds__(256,2) k_gemm(float* __restrict__ out){
    constexpr int KD = (PHASE==0) ? KH : KI;   // GEMM K dim
    constexpr int NB = (PHASE==0) ? 2  : 1;    // number of B matrices
    constexpr int NI = (PHASE==0) ? 4  : 8;    // n-frags (8 cols) per warp per matrix
    constexpr int NT = (PHASE==0) ? 64 : 128;  // N cols per matrix per CTA
    constexpr int KS = KD/64;
    constexpr int AST = 128*64;                // halves per A stage
    constexpr int BST = 128*64;                // halves per B stage (128 rows total)

    const int e  = blockIdx.z;
    const int cnt = g_cnt[e];
    const int m0 = blockIdx.x*128;             // m fastest-varying
    if(m0 >= cnt) return;
    const int n0 = blockIdx.y*NT;

    extern __shared__ __half sm[];
    __half* sA = sm;              // [3][128][64]
    __half* sW = sm + 3*AST;      // [3][128][64]
    __shared__ int      s_tok[128];
    __shared__ float    s_tw [128];
    __shared__ uint64_t s_mb[6];  // full[0..2], empty[3..5]

    const int tid = threadIdx.x;
    const uint32_t mb = smem_u32(s_mb);
    if(tid < 128){
        int r = min(m0+tid, cnt-1);
        s_tok[tid] = g_tok[e*KT + r];
        if(PHASE==0) s_tw[tid] = g_tw[e*KT + r];
    }
    if(tid==0){
        #pragma unroll
        for(int i=0;i<3;i++){
            mbar_init(mb + 8*i,      256);  // full: every thread cp-arrives (.noinc)
            mbar_init(mb + 8*(3+i),  8);    // empty: one arrive per warp
        }
    }
    __syncthreads();

    const __half* Wp0 = (PHASE==0) ? (g_W1 + (size_t)e*KI*KH) : (g_W2 + (size_t)e*KH*KI);
    const __half* Wp1 = g_W3 + (size_t)e*KI*KH;

    // producer: wait empty, issue 8 cp.async, noinc-arrive at full on completion
    auto produce = [&](int L){
        const int st = L%3, k0 = L*64;
        mbar_wait(mb + 8*(3+st), ((L/3)&1)^1);   // fresh barrier passes parity 1
        uint32_t baseA = smem_u32(sA + st*AST);
        #pragma unroll
        for(int it=0; it<4; it++){
            int c = it*256 + tid;
            int row = c>>3, cb = c&7;
            int sc = cb ^ (row&7);
            const __half* src = (PHASE==0)
                ? (g_X  + (size_t)s_tok[row]*KH + k0 + cb*8)
                : (g_Hb + (size_t)(e*KT + m0 + row)*KI + k0 + cb*8);
            cp16(baseA + row*128 + sc*16, src);
        }
        uint32_t baseW = smem_u32(sW + st*BST);
        #pragma unroll
        for(int it=0; it<4; it++){             // 128 B rows total
            int c = it*256 + tid;
            int row = c>>3, cb = c&7;
            int sc = cb ^ (row&7);
            const __half* W = (PHASE==0 && row>=64) ? Wp1 : Wp0;
            int wrow = (PHASE==0) ? (row&63) : row;
            cp16(baseW + row*128 + sc*16, W + (size_t)(n0+wrow)*KD + k0 + cb*8);
        }
        cp_mbar_arrive(mb + 8*st);
    };

    float acc[NB][2][NI][4];
    #pragma unroll
    for(int b=0;b<NB;b++)
        #pragma unroll
        for(int mi=0;mi<2;mi++)
            #pragma unroll
            for(int ni=0;ni<NI;ni++)
                #pragma unroll
                for(int k=0;k<4;k++) acc[b][mi][ni][k]=0.f;

    const int lane = tid & 31, warp = tid >> 5;
    const int wm = (warp>>1)*32, wn = (warp&1)*(NI*8);

    // hoisted fragment addressing (row&7 == lane&7 for every fragment)
    uint32_t kx[4];
    #pragma unroll
    for(int km=0;km<4;km++) kx[km] = (uint32_t)(((km*2 + (lane>>4)) ^ (lane&7))*16);
    uint32_t aoff[2], boff[NB*NI/2];
    #pragma unroll
    for(int mi=0;mi<2;mi++) aoff[mi] = (uint32_t)((wm + mi*16 + (lane&15))*128);
    #pragma unroll
    for(int b=0;b<NB;b++)
        #pragma unroll
        for(int nb=0;nb<NI/2;nb++)
            boff[b*(NI/2)+nb] = (uint32_t)(b*64*128 + (wn + nb*16 + (lane&15))*128);

    auto compute = [&](int st){
        uint32_t baseA = smem_u32(sA + st*AST);
        uint32_t baseW = smem_u32(sW + st*BST);
        #pragma unroll
        for(int km=0; km<4; km++){
            uint32_t a[2][4];
            #pragma unroll
            for(int mi=0;mi<2;mi++)
                ldsm4(a[mi], baseA + aoff[mi] + kx[km]);
            #pragma unroll
            for(int b=0;b<NB;b++){
                uint32_t bf[NI][2];
                #pragma unroll
                for(int nb=0;nb<NI/2;nb++){
                    uint32_t r[4];
                    ldsm4(r, baseW + boff[b*(NI/2)+nb] + kx[km]);
                    bf[nb*2  ][0]=r[0]; bf[nb*2+1][0]=r[1];
                    bf[nb*2  ][1]=r[2]; bf[nb*2+1][1]=r[3];
                }
                #pragma unroll
                for(int mi=0;mi<2;mi++)
                    #pragma unroll
                    for(int ni=0;ni<NI;ni++)
                        mma16(acc[b][mi][ni], a[mi], bf[ni][0], bf[ni][1]);
            }
        }
    };

    produce(0); produce(1);
    for(int ks=0; ks<KS; ks++){
        const int st = ks%3;
        mbar_wait(mb + 8*st, (ks/3)&1);     // consumer: wait stage full
        compute(st);
        if(lane==0) mbar_arrive(mb + 8*(3+st));  // warp done with stage
        if(ks+2<KS) produce(ks+2);
    }

    // epilogue
    #pragma unroll
    for(int mi=0;mi<2;mi++){
        #pragma unroll
        for(int hh=0;hh<2;hh++){
            int row = wm + mi*16 + (lane>>2) + hh*8;
            int r   = m0 + row;
            if(PHASE==0){
                float tw = (r < cnt) ? s_tw[row] : 0.f;
                __half* dst = g_Hb + (size_t)(e*KT + r)*KI + n0;
                #pragma unroll
                for(int ni=0;ni<NI;ni++){
                    int col = wn + ni*8 + (lane&3)*2;
                    float gg0 = acc[0][mi][ni][hh*2], gg1 = acc[0][mi][ni][hh*2+1];
                    float uu0 = acc[NB-1][mi][ni][hh*2], uu1 = acc[NB-1][mi][ni][hh*2+1];
                    float h0 = tw * (gg0/(1.f+__expf(-gg0))) * uu0;
                    float h1 = tw * (gg1/(1.f+__expf(-gg1))) * uu1;
                    *(__half2*)(dst + col) = __floats2half2_rn(h0,h1);
                }
            } else {
                if(r < cnt){
                    int t = s_tok[row];
                    float* dst = out + (size_t)t*KH + n0;
                    #pragma unroll
                    for(int ni=0;ni<NI;ni++){
                        int col = wn + ni*8 + (lane&3)*2;
                        atomicAdd(dst + col    , acc[0][mi][ni][hh*2  ]);
                        atomicAdd(dst + col + 1, acc[0][mi][ni][hh*2+1]);
                    }
                }
            }
        }
    }
}

// ---------- launch ----------
extern "C" void kernel_launch(void* const* d_in, const int* in_sizes, int n_in,
                              void* d_out, int out_size){
    const float* hs = (const float*)d_in[0];
    const float* lg = (const float*)d_in[1];
    const float* w1 = (const float*)d_in[2];
    const float* w2 = (const float*)d_in[3];
    const float* w3 = (const float*)d_in[4];
    float* out = (float*)d_out;

    const int DS = 3*(128*64 + 128*64)*2;  // 98304 B (both phases)
    cudaFuncSetAttribute(k_gemm<0>, cudaFuncAttributeMaxDynamicSharedMemorySize, DS);
    cudaFuncSetAttribute(k_gemm<1>, cudaFuncAttributeMaxDynamicSharedMemorySize, DS);

    // keep k_gemm<0> at launch #4 (ncu profile target)
    k_cvtx  <<<2048, 256>>>((const float4*)hs);                      // 1 (also zeroes g_cnt)
    k_route <<<KT/256, 256>>>(lg);                                   // 2
    k_cvtw13<<<4096, 256>>>((const float4*)w1, (const float4*)w3);   // 3

    dim3 gA(KT/128, KI/64, KE);   // m fastest
    k_gemm<0><<<gA, 256, DS>>>(out);                                 // 4  <- profile target

    k_cvtw2 <<<4096, 256>>>((const float4*)w2);                      // 5
    k_zero  <<<512, 256>>>((float4*)out);                            // 6

    dim3 gB(KT/128, KH/128, KE);  // m fastest
    k_gemm<1><<<gB, 256, DS>>>(out);                                 // 7
}

// round 13
// speedup vs baseline: 1.0421x; 1.0304x over previous
#include <cuda_runtime.h>
#include <cuda_fp16.h>
#include <cstdint>
#include <cstddef>

#define KT 8192
#define KE 8
#define KH 2048
#define KI 5632

// ---------- device scratch (static, no allocs) ----------
__device__ __align__(256) __half g_X [(size_t)KT*KH];
__device__ __align__(256) __half g_W1[(size_t)KE*KI*KH];
__device__ __align__(256) __half g_W3[(size_t)KE*KI*KH];
__device__ __align__(256) __half g_W2[(size_t)KE*KH*KI];
__device__ __align__(256) __half g_Hb[(size_t)KE*KT*KI];
__device__ int   g_cnt[KE];
__device__ int   g_tok[KE*KT];
__device__ float g_tw [KE*KT];

// ---------- helpers ----------
__device__ __forceinline__ uint32_t smem_u32(const void* p){
    return (uint32_t)__cvta_generic_to_shared(p);
}
__device__ __forceinline__ void cp16(uint32_t dst, const void* src){
    asm volatile("cp.async.cg.shared.global [%0], [%1], 16;" :: "r"(dst), "l"(src));
}
__device__ __forceinline__ void cp_commit(){ asm volatile("cp.async.commit_group;"); }
template<int N> __device__ __forceinline__ void cp_wait(){
    asm volatile("cp.async.wait_group %0;" :: "n"(N));
}
__device__ __forceinline__ void ldsm4(uint32_t* r, uint32_t a){
    asm volatile("ldmatrix.sync.aligned.m8n8.x4.shared.b16 {%0,%1,%2,%3}, [%4];"
                 : "=r"(r[0]),"=r"(r[1]),"=r"(r[2]),"=r"(r[3]) : "r"(a));
}
__device__ __forceinline__ void mma16(float* d, const uint32_t* a, uint32_t b0, uint32_t b1){
    asm volatile("mma.sync.aligned.m16n8k16.row.col.f32.f16.f16.f32 "
                 "{%0,%1,%2,%3}, {%4,%5,%6,%7}, {%8,%9}, {%0,%1,%2,%3};"
                 : "+f"(d[0]),"+f"(d[1]),"+f"(d[2]),"+f"(d[3])
                 : "r"(a[0]),"r"(a[1]),"r"(a[2]),"r"(a[3]),"r"(b0),"r"(b1));
}

// ---------- routing: top-2 + softmax + compaction ----------
__global__ void k_route(const float* __restrict__ lg){
    int t = blockIdx.x*blockDim.x + threadIdx.x;
    if(t>=KT) return;
    float v[KE];
    #pragma unroll
    for(int e=0;e<KE;e++) v[e]=lg[t*KE+e];
    int i0=0;
    #pragma unroll
    for(int e=1;e<KE;e++) if(v[e]>v[i0]) i0=e;
    int i1=-1;
    #pragma unroll
    for(int e=0;e<KE;e++){ if(e==i0) continue; if(i1<0 || v[e]>v[i1]) i1=e; }
    float wa = 1.f/(1.f + __expf(v[i1]-v[i0]));
    float wb = 1.f - wa;
    int s0 = atomicAdd(&g_cnt[i0],1);
    g_tok[i0*KT+s0]=t; g_tw[i0*KT+s0]=wa;
    int s1 = atomicAdd(&g_cnt[i1],1);
    g_tok[i1*KT+s1]=t; g_tw[i1*KT+s1]=wb;
}

// ---------- fp32 -> fp16 conversions ----------
__global__ void k_cvtx(const float4* __restrict__ s){
    if(blockIdx.x==0 && threadIdx.x<KE) g_cnt[threadIdx.x]=0;  // reset counts for k_route
    __half2* d = (__half2*)g_X;
    int i = blockIdx.x*blockDim.x + threadIdx.x;
    const int n4 = KT*KH/4;
    for(int j=i;j<n4;j+=gridDim.x*blockDim.x){
        float4 a = s[j];
        d[2*j  ] = __floats2half2_rn(a.x,a.y);
        d[2*j+1] = __floats2half2_rn(a.z,a.w);
    }
}
__global__ void k_cvtw13(const float4* __restrict__ s1, const float4* __restrict__ s3){
    __half2* d1 = (__half2*)g_W1;
    __half2* d3 = (__half2*)g_W3;
    int i = blockIdx.x*blockDim.x + threadIdx.x;
    const int n4 = KE*KI*KH/4;
    for(int j=i;j<n4;j+=gridDim.x*blockDim.x){
        float4 a = s1[j];
        d1[2*j  ] = __floats2half2_rn(a.x,a.y);
        d1[2*j+1] = __floats2half2_rn(a.z,a.w);
        float4 b = s3[j];
        d3[2*j  ] = __floats2half2_rn(b.x,b.y);
        d3[2*j+1] = __floats2half2_rn(b.z,b.w);
    }
}
// converts W2 AND zeroes the output buffer (merged former k_zero)
__global__ void k_cvtw2z(const float4* __restrict__ s, float4* __restrict__ out){
    __half2* d = (__half2*)g_W2;
    int i = blockIdx.x*blockDim.x + threadIdx.x;
    const int n4 = KE*KH*KI/4;
    const int stride = gridDim.x*blockDim.x;
    for(int j=i;j<n4;j+=stride){
        float4 a = s[j];
        d[2*j  ] = __floats2half2_rn(a.x,a.y);
        d[2*j+1] = __floats2half2_rn(a.z,a.w);
    }
    const int z4 = KT*KH/4;
    float4 z = make_float4(0.f,0.f,0.f,0.f);
    for(int j=i;j<z4;j+=stride) out[j]=z;
}

// ---------- GEMM: PHASE 0 = gate/up (silu*up*tw -> g_Hb fp16), N=64 x {W1,W3}
//                  PHASE 1 = down-proj (atomicAdd -> out), N=128 x W2
// CTA tile 128(M) x 128(B-rows) x 64(K); 8 warps, warp tile 32x(64*NB); 3-stage
template<int PHASE>
__global__ void __launch_bounds__(256,2) k_gemm(float* __restrict__ out){
    constexpr int KD = (PHASE==0) ? KH : KI;   // GEMM K dim
    constexpr int NB = (PHASE==0) ? 2  : 1;    // number of B matrices
    constexpr int NI = (PHASE==0) ? 4  : 8;    // n-frags (8 cols) per warp per matrix
    constexpr int NT = (PHASE==0) ? 64 : 128;  // N cols per matrix per CTA
    constexpr int KS = KD/64;
    constexpr int AST = 128*64;                // halves per A stage
    constexpr int BST = 128*64;                // halves per B stage (128 rows total)

    const int e  = blockIdx.z;
    const int cnt = g_cnt[e];
    const int m0 = blockIdx.x*128;             // m fastest-varying
    if(m0 >= cnt) return;
    const int n0 = blockIdx.y*NT;

    extern __shared__ __half sm[];
    __half* sA = sm;              // [3][128][64]
    __half* sW = sm + 3*AST;      // [3][128][64]
    __shared__ int   s_tok[128];
    __shared__ float s_tw [128];

    const int tid = threadIdx.x;
    if(tid < 128){
        int r = min(m0+tid, cnt-1);
        s_tok[tid] = g_tok[e*KT + r];
        if(PHASE==0) s_tw[tid] = g_tw[e*KT + r];
    }
    __syncthreads();

    const __half* Wp0 = (PHASE==0) ? (g_W1 + (size_t)e*KI*KH) : (g_W2 + (size_t)e*KH*KI);
    const __half* Wp1 = g_W3 + (size_t)e*KI*KH;

    auto load_stage = [&](int L){
        const int st = L%3, k0 = L*64;
        uint32_t baseA = smem_u32(sA + st*AST);
        #pragma unroll
        for(int it=0; it<4; it++){
            int c = it*256 + tid;
            int row = c>>3, cb = c&7;
            int sc = cb ^ (row&7);
            const __half* src = (PHASE==0)
                ? (g_X  + (size_t)s_tok[row]*KH + k0 + cb*8)
                : (g_Hb + (size_t)(e*KT + m0 + row)*KI + k0 + cb*8);
            cp16(baseA + row*128 + sc*16, src);
        }
        uint32_t baseW = smem_u32(sW + st*BST);
        #pragma unroll
        for(int it=0; it<4; it++){             // 128 B rows total
            int c = it*256 + tid;
            int row = c>>3, cb = c&7;
            int sc = cb ^ (row&7);
            const __half* W = (PHASE==0 && row>=64) ? Wp1 : Wp0;
            int wrow = (PHASE==0) ? (row&63) : row;
            cp16(baseW + row*128 + sc*16, W + (size_t)(n0+wrow)*KD + k0 + cb*8);
        }
        cp_commit();
    };

    float acc[NB][2][NI][4];
    #pragma unroll
    for(int b=0;b<NB;b++)
        #pragma unroll
        for(int mi=0;mi<2;mi++)
            #pragma unroll
            for(int ni=0;ni<NI;ni++)
                #pragma unroll
                for(int k=0;k<4;k++) acc[b][mi][ni][k]=0.f;

    const int lane = tid & 31, warp = tid >> 5;
    const int wm = (warp>>1)*32, wn = (warp&1)*(NI*8);

    auto compute = [&](int st){
        uint32_t baseA = smem_u32(sA + st*AST);
        uint32_t baseW = smem_u32(sW + st*BST);
        #pragma unroll
        for(int km=0; km<4; km++){
            uint32_t a[2][4];
            #pragma unroll
            for(int mi=0;mi<2;mi++){
                int row = wm + mi*16 + (lane&15);
                int c   = km*2 + (lane>>4);
                int sc  = c ^ (row&7);
                ldsm4(a[mi], baseA + row*128 + sc*16);
            }
            #pragma unroll
            for(int b=0;b<NB;b++){
                uint32_t bw = baseW + b*64*128;
                uint32_t bf[NI][2];
                #pragma unroll
                for(int nb=0;nb<NI/2;nb++){
                    int row = wn + nb*16 + (lane&15);
                    int c   = km*2 + (lane>>4);
                    int sc  = c ^ (row&7);
                    uint32_t r[4];
                    ldsm4(r, bw + row*128 + sc*16);
                    bf[nb*2  ][0]=r[0]; bf[nb*2+1][0]=r[1];
                    bf[nb*2  ][1]=r[2]; bf[nb*2+1][1]=r[3];
                }
                #pragma unroll
                for(int mi=0;mi<2;mi++)
                    #pragma unroll
                    for(int ni=0;ni<NI;ni++)
                        mma16(acc[b][mi][ni], a[mi], bf[ni][0], bf[ni][1]);
            }
        }
    };

    load_stage(0); load_stage(1);
    #pragma unroll 3
    for(int ks=0; ks<KS; ks++){
        if(ks+1<KS) cp_wait<1>(); else cp_wait<0>();
        __syncthreads();
        if(ks+2<KS) load_stage(ks+2);   // overlapped with compute below
        compute(ks%3);
    }

    // epilogue
    #pragma unroll
    for(int mi=0;mi<2;mi++){
        #pragma unroll
        for(int hh=0;hh<2;hh++){
            int row = wm + mi*16 + (lane>>2) + hh*8;
            int r   = m0 + row;
            if(PHASE==0){
                float tw = (r < cnt) ? s_tw[row] : 0.f;
                __half* dst = g_Hb + (size_t)(e*KT + r)*KI + n0;
                #pragma unroll
                for(int ni=0;ni<NI;ni++){
                    int col = wn + ni*8 + (lane&3)*2;
                    float gg0 = acc[0][mi][ni][hh*2], gg1 = acc[0][mi][ni][hh*2+1];
                    float uu0 = acc[NB-1][mi][ni][hh*2], uu1 = acc[NB-1][mi][ni][hh*2+1];
                    float h0 = tw * (gg0/(1.f+__expf(-gg0))) * uu0;
                    float h1 = tw * (gg1/(1.f+__expf(-gg1))) * uu1;
                    *(__half2*)(dst + col) = __floats2half2_rn(h0,h1);
                }
            } else {
                if(r < cnt){
                    int t = s_tok[row];
                    float* dst = out + (size_t)t*KH + n0;
                    #pragma unroll
                    for(int ni=0;ni<NI;ni++){
                        int col = wn + ni*8 + (lane&3)*2;
                        atomicAdd(dst + col    , acc[0][mi][ni][hh*2  ]);
                        atomicAdd(dst + col + 1, acc[0][mi][ni][hh*2+1]);
                    }
                }
            }
        }
    }
}

// ---------- launch ----------
extern "C" void kernel_launch(void* const* d_in, const int* in_sizes, int n_in,
                              void* d_out, int out_size){
    const float* hs = (const float*)d_in[0];
    const float* lg = (const float*)d_in[1];
    const float* w1 = (const float*)d_in[2];
    const float* w2 = (const float*)d_in[3];
    const float* w3 = (const float*)d_in[4];
    float* out = (float*)d_out;

    const int DS = 3*(128*64 + 128*64)*2;  // 98304 B (both phases)
    cudaFuncSetAttribute(k_gemm<0>, cudaFuncAttributeMaxDynamicSharedMemorySize, DS);
    cudaFuncSetAttribute(k_gemm<1>, cudaFuncAttributeMaxDynamicSharedMemorySize, DS);

    // keep k_gemm<0> at launch #4 (ncu profile target)
    k_cvtx  <<<2048, 256>>>((const float4*)hs);                      // 1 (also zeroes g_cnt)
    k_route <<<KT/256, 256>>>(lg);                                   // 2
    k_cvtw13<<<4096, 256>>>((const float4*)w1, (const float4*)w3);   // 3

    dim3 gA(KT/128, KI/64, KE);   // m fastest
    k_gemm<0><<<gA, 256, DS>>>(out);                                 // 4  <- profile target

    k_cvtw2z<<<4096, 256>>>((const float4*)w2, (float4*)out);        // 5 (cvt W2 + zero out)

    dim3 gB(KT/128, KH/128, KE);  // m fastest
    k_gemm<1><<<gB, 256, DS>>>(out);                                 // 6
}

// round 14
// speedup vs baseline: 1.0597x; 1.0169x over previous
#include <cuda_runtime.h>
#include <cuda_fp16.h>
#include <cstdint>
#include <cstddef>

#define KT 8192
#define KE 8
#define KH 2048
#define KI 5632

// ---------- device scratch (static, no allocs) ----------
__device__ __align__(256) __half g_X [(size_t)KT*KH];
__device__ __align__(256) __half g_W1[(size_t)KE*KI*KH];
__device__ __align__(256) __half g_W3[(size_t)KE*KI*KH];
__device__ __align__(256) __half g_W2[(size_t)KE*KH*KI];
__device__ __align__(256) __half g_Hb[(size_t)KE*KT*KI];
__device__ int   g_cnt[KE];
__device__ int   g_tok[KE*KT];
__device__ float g_tw [KE*KT];

// ---------- helpers ----------
__device__ __forceinline__ uint32_t smem_u32(const void* p){
    return (uint32_t)__cvta_generic_to_shared(p);
}
__device__ __forceinline__ void cp16(uint32_t dst, const void* src){
    asm volatile("cp.async.cg.shared.global [%0], [%1], 16;" :: "r"(dst), "l"(src));
}
__device__ __forceinline__ void cp_commit(){ asm volatile("cp.async.commit_group;"); }
template<int N> __device__ __forceinline__ void cp_wait(){
    asm volatile("cp.async.wait_group %0;" :: "n"(N));
}
__device__ __forceinline__ void ldsm4(uint32_t* r, uint32_t a){
    asm volatile("ldmatrix.sync.aligned.m8n8.x4.shared.b16 {%0,%1,%2,%3}, [%4];"
                 : "=r"(r[0]),"=r"(r[1]),"=r"(r[2]),"=r"(r[3]) : "r"(a));
}
__device__ __forceinline__ void mma16(float* d, const uint32_t* a, uint32_t b0, uint32_t b1){
    asm volatile("mma.sync.aligned.m16n8k16.row.col.f32.f16.f16.f32 "
                 "{%0,%1,%2,%3}, {%4,%5,%6,%7}, {%8,%9}, {%0,%1,%2,%3};"
                 : "+f"(d[0]),"+f"(d[1]),"+f"(d[2]),"+f"(d[3])
                 : "r"(a[0]),"r"(a[1]),"r"(a[2]),"r"(a[3]),"r"(b0),"r"(b1));
}

// ---------- routing: top-2 + softmax + compaction ----------
__global__ void k_route(const float* __restrict__ lg){
    int t = blockIdx.x*blockDim.x + threadIdx.x;
    if(t>=KT) return;
    float v[KE];
    #pragma unroll
    for(int e=0;e<KE;e++) v[e]=lg[t*KE+e];
    int i0=0;
    #pragma unroll
    for(int e=1;e<KE;e++) if(v[e]>v[i0]) i0=e;
    int i1=-1;
    #pragma unroll
    for(int e=0;e<KE;e++){ if(e==i0) continue; if(i1<0 || v[e]>v[i1]) i1=e; }
    float wa = 1.f/(1.f + __expf(v[i1]-v[i0]));
    float wb = 1.f - wa;
    int s0 = atomicAdd(&g_cnt[i0],1);
    g_tok[i0*KT+s0]=t; g_tw[i0*KT+s0]=wa;
    int s1 = atomicAdd(&g_cnt[i1],1);
    g_tok[i1*KT+s1]=t; g_tw[i1*KT+s1]=wb;
}

// ---------- fp32 -> fp16 conversions ----------
__global__ void k_cvtx(const float4* __restrict__ s){
    if(blockIdx.x==0 && threadIdx.x<KE) g_cnt[threadIdx.x]=0;  // reset counts for k_route
    __half2* d = (__half2*)g_X;
    int i = blockIdx.x*blockDim.x + threadIdx.x;
    const int n4 = KT*KH/4;
    for(int j=i;j<n4;j+=gridDim.x*blockDim.x){
        float4 a = s[j];
        d[2*j  ] = __floats2half2_rn(a.x,a.y);
        d[2*j+1] = __floats2half2_rn(a.z,a.w);
    }
}
__global__ void k_cvtw13(const float4* __restrict__ s1, const float4* __restrict__ s3){
    __half2* d1 = (__half2*)g_W1;
    __half2* d3 = (__half2*)g_W3;
    int i = blockIdx.x*blockDim.x + threadIdx.x;
    const int n4 = KE*KI*KH/4;
    for(int j=i;j<n4;j+=gridDim.x*blockDim.x){
        float4 a = s1[j];
        d1[2*j  ] = __floats2half2_rn(a.x,a.y);
        d1[2*j+1] = __floats2half2_rn(a.z,a.w);
        float4 b = s3[j];
        d3[2*j  ] = __floats2half2_rn(b.x,b.y);
        d3[2*j+1] = __floats2half2_rn(b.z,b.w);
    }
}

// ---------- GEMM: PHASE 0 = gate/up (silu*up*tw -> g_Hb fp16), N=64 x {W1,W3}
//                  + piggy-back blocks (y == gridDim.y-1): cvt W2 + zero out,
//                    overlapping the DRAM-idle GEMM (W2/out unused by phase 0)
//                  PHASE 1 = down-proj (atomicAdd -> out), N=128 x W2
// CTA tile 128(M) x 128(B-rows) x 64(K); 8 warps, warp tile 32x(64*NB); 3-stage
template<int PHASE>
__global__ void __launch_bounds__(256,2) k_gemm(float* __restrict__ out,
                                                const float4* __restrict__ w2src){
    constexpr int KD = (PHASE==0) ? KH : KI;   // GEMM K dim
    constexpr int NB = (PHASE==0) ? 2  : 1;    // number of B matrices
    constexpr int NI = (PHASE==0) ? 4  : 8;    // n-frags (8 cols) per warp per matrix
    constexpr int NT = (PHASE==0) ? 64 : 128;  // N cols per matrix per CTA
    constexpr int KS = KD/64;
    constexpr int AST = 128*64;                // halves per A stage
    constexpr int BST = 128*64;                // halves per B stage (128 rows total)

    if(PHASE==0 && blockIdx.y == gridDim.y-1){
        // piggy-back: convert W2 fp32->fp16 and zero the output buffer
        const int i    = (blockIdx.z*gridDim.x + blockIdx.x)*blockDim.x + threadIdx.x;
        const int nthr = gridDim.z*gridDim.x*blockDim.x;
        __half2* d = (__half2*)g_W2;
        const int n4 = KE*KH*KI/4;
        for(int j=i;j<n4;j+=nthr){
            float4 a = w2src[j];
            d[2*j  ] = __floats2half2_rn(a.x,a.y);
            d[2*j+1] = __floats2half2_rn(a.z,a.w);
        }
        float4* ov = (float4*)out;
        const int z4 = KT*KH/4;
        float4 z = make_float4(0.f,0.f,0.f,0.f);
        for(int j=i;j<z4;j+=nthr) ov[j]=z;
        return;
    }

    const int e  = blockIdx.z;
    const int cnt = g_cnt[e];
    const int m0 = blockIdx.x*128;             // m fastest-varying
    if(m0 >= cnt) return;
    const int n0 = blockIdx.y*NT;

    extern __shared__ __half sm[];
    __half* sA = sm;              // [3][128][64]
    __half* sW = sm + 3*AST;      // [3][128][64]
    __shared__ int   s_tok[128];
    __shared__ float s_tw [128];

    const int tid = threadIdx.x;
    if(tid < 128){
        int r = min(m0+tid, cnt-1);
        s_tok[tid] = g_tok[e*KT + r];
        if(PHASE==0) s_tw[tid] = g_tw[e*KT + r];
    }
    __syncthreads();

    const __half* Wp0 = (PHASE==0) ? (g_W1 + (size_t)e*KI*KH) : (g_W2 + (size_t)e*KH*KI);
    const __half* Wp1 = g_W3 + (size_t)e*KI*KH;

    auto load_stage = [&](int L){
        const int st = L%3, k0 = L*64;
        uint32_t baseA = smem_u32(sA + st*AST);
        #pragma unroll
        for(int it=0; it<4; it++){
            int c = it*256 + tid;
            int row = c>>3, cb = c&7;
            int sc = cb ^ (row&7);
            const __half* src = (PHASE==0)
                ? (g_X  + (size_t)s_tok[row]*KH + k0 + cb*8)
                : (g_Hb + (size_t)(e*KT + m0 + row)*KI + k0 + cb*8);
            cp16(baseA + row*128 + sc*16, src);
        }
        uint32_t baseW = smem_u32(sW + st*BST);
        #pragma unroll
        for(int it=0; it<4; it++){             // 128 B rows total
            int c = it*256 + tid;
            int row = c>>3, cb = c&7;
            int sc = cb ^ (row&7);
            const __half* W = (PHASE==0 && row>=64) ? Wp1 : Wp0;
            int wrow = (PHASE==0) ? (row&63) : row;
            cp16(baseW + row*128 + sc*16, W + (size_t)(n0+wrow)*KD + k0 + cb*8);
        }
        cp_commit();
    };

    float acc[NB][2][NI][4];
    #pragma unroll
    for(int b=0;b<NB;b++)
        #pragma unroll
        for(int mi=0;mi<2;mi++)
            #pragma unroll
            for(int ni=0;ni<NI;ni++)
                #pragma unroll
                for(int k=0;k<4;k++) acc[b][mi][ni][k]=0.f;

    const int lane = tid & 31, warp = tid >> 5;
    const int wm = (warp>>1)*32, wn = (warp&1)*(NI*8);

    auto compute = [&](int st){
        uint32_t baseA = smem_u32(sA + st*AST);
        uint32_t baseW = smem_u32(sW + st*BST);
        #pragma unroll
        for(int km=0; km<4; km++){
            uint32_t a[2][4];
            #pragma unroll
            for(int mi=0;mi<2;mi++){
                int row = wm + mi*16 + (lane&15);
                int c   = km*2 + (lane>>4);
                int sc  = c ^ (row&7);
                ldsm4(a[mi], baseA + row*128 + sc*16);
            }
            #pragma unroll
            for(int b=0;b<NB;b++){
                uint32_t bw = baseW + b*64*128;
                uint32_t bf[NI][2];
                #pragma unroll
                for(int nb=0;nb<NI/2;nb++){
                    int row = wn + nb*16 + (lane&15);
                    int c   = km*2 + (lane>>4);
                    int sc  = c ^ (row&7);
                    uint32_t r[4];
                    ldsm4(r, bw + row*128 + sc*16);
                    bf[nb*2  ][0]=r[0]; bf[nb*2+1][0]=r[1];
                    bf[nb*2  ][1]=r[2]; bf[nb*2+1][1]=r[3];
                }
                #pragma unroll
                for(int mi=0;mi<2;mi++)
                    #pragma unroll
                    for(int ni=0;ni<NI;ni++)
                        mma16(acc[b][mi][ni], a[mi], bf[ni][0], bf[ni][1]);
            }
        }
    };

    load_stage(0); load_stage(1);
    #pragma unroll 3
    for(int ks=0; ks<KS; ks++){
        if(ks+1<KS) cp_wait<1>(); else cp_wait<0>();
        __syncthreads();
        if(ks+2<KS) load_stage(ks+2);   // overlapped with compute below
        compute(ks%3);
    }

    // epilogue
    #pragma unroll
    for(int mi=0;mi<2;mi++){
        #pragma unroll
        for(int hh=0;hh<2;hh++){
            int row = wm + mi*16 + (lane>>2) + hh*8;
            int r   = m0 + row;
            if(PHASE==0){
                float tw = (r < cnt) ? s_tw[row] : 0.f;
                __half* dst = g_Hb + (size_t)(e*KT + r)*KI + n0;
                #pragma unroll
                for(int ni=0;ni<NI;ni++){
                    int col = wn + ni*8 + (lane&3)*2;
                    float gg0 = acc[0][mi][ni][hh*2], gg1 = acc[0][mi][ni][hh*2+1];
                    float uu0 = acc[NB-1][mi][ni][hh*2], uu1 = acc[NB-1][mi][ni][hh*2+1];
                    float h0 = tw * (gg0/(1.f+__expf(-gg0))) * uu0;
                    float h1 = tw * (gg1/(1.f+__expf(-gg1))) * uu1;
                    *(__half2*)(dst + col) = __floats2half2_rn(h0,h1);
                }
            } else {
                if(r < cnt){
                    int t = s_tok[row];
                    float* dst = out + (size_t)t*KH + n0;
                    #pragma unroll
                    for(int ni=0;ni<NI;ni++){
                        int col = wn + ni*8 + (lane&3)*2;
                        atomicAdd(dst + col    , acc[0][mi][ni][hh*2  ]);
                        atomicAdd(dst + col + 1, acc[0][mi][ni][hh*2+1]);
                    }
                }
            }
        }
    }
}

// ---------- launch ----------
extern "C" void kernel_launch(void* const* d_in, const int* in_sizes, int n_in,
                              void* d_out, int out_size){
    const float* hs = (const float*)d_in[0];
    const float* lg = (const float*)d_in[1];
    const float* w1 = (const float*)d_in[2];
    const float* w2 = (const float*)d_in[3];
    const float* w3 = (const float*)d_in[4];
    float* out = (float*)d_out;

    const int DS = 3*(128*64 + 128*64)*2;  // 98304 B (both phases)
    cudaFuncSetAttribute(k_gemm<0>, cudaFuncAttributeMaxDynamicSharedMemorySize, DS);
    cudaFuncSetAttribute(k_gemm<1>, cudaFuncAttributeMaxDynamicSharedMemorySize, DS);

    // keep k_gemm<0> at launch #4 (ncu profile target)
    k_cvtx  <<<2048, 256>>>((const float4*)hs);                      // 1 (also zeroes g_cnt)
    k_route <<<KT/256, 256>>>(lg);                                   // 2
    k_cvtw13<<<4096, 256>>>((const float4*)w1, (const float4*)w3);   // 3

    // y = KI/64 GEMM n-tiles + 1 piggy-back row (cvt W2 + zero out)
    dim3 gA(KT/128, KI/64 + 1, KE);   // m fastest
    k_gemm<0><<<gA, 256, DS>>>(out, (const float4*)w2);              // 4  <- profile target

    dim3 gB(KT/128, KH/128, KE);  // m fastest
    k_gemm<1><<<gB, 256, DS>>>(out, nullptr);                        // 5
}

// round 15
// speedup vs baseline: 1.0609x; 1.0012x over previous
#include <cuda_runtime.h>
#include <cuda_fp16.h>
#include <cstdint>
#include <cstddef>

#define KT 8192
#define KE 8
#define KH 2048
#define KI 5632

// ---------- device scratch (static, no allocs) ----------
__device__ __align__(256) __half g_X [(size_t)KT*KH];
__device__ __align__(256) __half g_W1[(size_t)KE*KI*KH];
__device__ __align__(256) __half g_W3[(size_t)KE*KI*KH];
__device__ __align__(256) __half g_W2[(size_t)KE*KH*KI];
__device__ __align__(256) __half g_Hb[(size_t)KE*KT*KI];
__device__ int   g_cnt[KE];
__device__ int   g_done[KE];   // per-expert W1/W3 conversion completion counters
__device__ int   g_tok[KE*KT];
__device__ float g_tw [KE*KT];

// ---------- helpers ----------
__device__ __forceinline__ uint32_t smem_u32(const void* p){
    return (uint32_t)__cvta_generic_to_shared(p);
}
__device__ __forceinline__ void cp16(uint32_t dst, const void* src){
    asm volatile("cp.async.cg.shared.global [%0], [%1], 16;" :: "r"(dst), "l"(src));
}
__device__ __forceinline__ void cp_commit(){ asm volatile("cp.async.commit_group;"); }
template<int N> __device__ __forceinline__ void cp_wait(){
    asm volatile("cp.async.wait_group %0;" :: "n"(N));
}
__device__ __forceinline__ void ldsm4(uint32_t* r, uint32_t a){
    asm volatile("ldmatrix.sync.aligned.m8n8.x4.shared.b16 {%0,%1,%2,%3}, [%4];"
                 : "=r"(r[0]),"=r"(r[1]),"=r"(r[2]),"=r"(r[3]) : "r"(a));
}
__device__ __forceinline__ void mma16(float* d, const uint32_t* a, uint32_t b0, uint32_t b1){
    asm volatile("mma.sync.aligned.m16n8k16.row.col.f32.f16.f16.f32 "
                 "{%0,%1,%2,%3}, {%4,%5,%6,%7}, {%8,%9}, {%0,%1,%2,%3};"
                 : "+f"(d[0]),"+f"(d[1]),"+f"(d[2]),"+f"(d[3])
                 : "r"(a[0]),"r"(a[1]),"r"(a[2]),"r"(a[3]),"r"(b0),"r"(b1));
}

// ---------- routing: top-2 + softmax + compaction ----------
__global__ void k_route(const float* __restrict__ lg){
    int t = blockIdx.x*blockDim.x + threadIdx.x;
    if(t>=KT) return;
    float v[KE];
    #pragma unroll
    for(int e=0;e<KE;e++) v[e]=lg[t*KE+e];
    int i0=0;
    #pragma unroll
    for(int e=1;e<KE;e++) if(v[e]>v[i0]) i0=e;
    int i1=-1;
    #pragma unroll
    for(int e=0;e<KE;e++){ if(e==i0) continue; if(i1<0 || v[e]>v[i1]) i1=e; }
    float wa = 1.f/(1.f + __expf(v[i1]-v[i0]));
    float wb = 1.f - wa;
    int s0 = atomicAdd(&g_cnt[i0],1);
    g_tok[i0*KT+s0]=t; g_tw[i0*KT+s0]=wa;
    int s1 = atomicAdd(&g_cnt[i1],1);
    g_tok[i1*KT+s1]=t; g_tw[i1*KT+s1]=wb;
}

// ---------- fp32 -> fp16 conversion of X (+ per-call flag resets) ----------
__global__ void k_cvtx(const float4* __restrict__ s){
    if(blockIdx.x==0 && threadIdx.x<KE){
        g_cnt[threadIdx.x]=0;
        g_done[threadIdx.x]=0;
    }
    __half2* d = (__half2*)g_X;
    int i = blockIdx.x*blockDim.x + threadIdx.x;
    const int n4 = KT*KH/4;
    for(int j=i;j<n4;j+=gridDim.x*blockDim.x){
        float4 a = s[j];
        d[2*j  ] = __floats2half2_rn(a.x,a.y);
        d[2*j+1] = __floats2half2_rn(a.z,a.w);
    }
}

// ---------- GEMM: PHASE 0 = gate/up (silu*up*tw -> g_Hb fp16), N=64 x {W1,W3}
//   1-D grid with bid-ordered segments:
//     [cvt W1/W3 e0][gemm e0 head][cvt W1/W3 e1..7][gemm e0 rest][w2z]
//     [gemm e1][w2z] ... [gemm e7][w2z]
//   gemm blocks spin on g_done[e] (converters always at lower bids -> no deadlock)
//                  PHASE 1 = down-proj (atomicAdd -> out), N=128 x W2 (3-D grid)
// CTA tile 128(M) x 128(B-rows) x 64(K); 8 warps; 3-stage cp.async
template<int PHASE>
__global__ void __launch_bounds__(256,2) k_gemm(float* __restrict__ out,
                                                const float4* __restrict__ w1src,
                                                const float4* __restrict__ w3src,
                                                const float4* __restrict__ w2src){
    constexpr int KD = (PHASE==0) ? KH : KI;   // GEMM K dim
    constexpr int NB = (PHASE==0) ? 2  : 1;    // number of B matrices
    constexpr int NI = (PHASE==0) ? 4  : 8;    // n-frags (8 cols) per warp per matrix
    constexpr int NT = (PHASE==0) ? 64 : 128;  // N cols per matrix per CTA
    constexpr int KS = KD/64;
    constexpr int AST = 128*64;                // halves per A stage
    constexpr int BST = 128*64;                // halves per B stage (128 rows total)

    const int tid = threadIdx.x;
    int e, m0, n0;

    if(PHASE==0){
        // ---- segment decode (1-D grid) ----
        int bid = blockIdx.x;
        int gidx = -1, cvte = -1, cvtj = 0, cvtB = 0, w2j = -1;
        if(bid < 256){ cvte=0; cvtj=bid; cvtB=256; }
        else if(bid < 552){ gidx = bid-256; }
        else if(bid < 1000){ int r=bid-552; cvte=1+r/64; cvtj=r%64; cvtB=64; }
        else if(bid < 6336){ gidx = 296 + (bid-1000); }
        else if(bid < 6400){ w2j = bid-6336; }
        else { int r = bid-6400; int k = r/5696; int off = r%5696;
               if(off<5632) gidx = (k+1)*5632 + off;
               else w2j = (k+1)*64 + (off-5632); }

        if(cvte >= 0){
            // convert W1[cvte], W3[cvte] fp32 -> fp16, then publish flag
            const float4* s1 = w1src + (size_t)cvte*KI*KH/4;
            const float4* s3 = w3src + (size_t)cvte*KI*KH/4;
            __half2* d1 = (__half2*)(g_W1 + (size_t)cvte*KI*KH);
            __half2* d3 = (__half2*)(g_W3 + (size_t)cvte*KI*KH);
            const int n4 = KI*KH/4;
            for(int j=cvtj*256+tid; j<n4; j+=cvtB*256){
                float4 a = s1[j];
                d1[2*j  ] = __floats2half2_rn(a.x,a.y);
                d1[2*j+1] = __floats2half2_rn(a.z,a.w);
                float4 b = s3[j];
                d3[2*j  ] = __floats2half2_rn(b.x,b.y);
                d3[2*j+1] = __floats2half2_rn(b.z,b.w);
            }
            __syncthreads();
            __threadfence();
            if(tid==0) atomicAdd(&g_done[cvte], 1);
            return;
        }
        if(w2j >= 0){
            // piggy-back: convert W2 fp32->fp16 and zero the output (for gemm1)
            __half2* d = (__half2*)g_W2;
            const int n4 = KE*KH*KI/4;
            const int nthr = 512*256;
            for(int j=w2j*256+tid; j<n4; j+=nthr){
                float4 a = w2src[j];
                d[2*j  ] = __floats2half2_rn(a.x,a.y);
                d[2*j+1] = __floats2half2_rn(a.z,a.w);
            }
            float4* ov = (float4*)out;
            const int z4 = KT*KH/4;
            float4 z = make_float4(0.f,0.f,0.f,0.f);
            for(int j=w2j*256+tid; j<z4; j+=nthr) ov[j]=z;
            return;
        }
        e  = gidx / 5632;
        int rem = gidx % 5632;
        n0 = (rem/64)*64;
        m0 = (rem%64)*128;
    } else {
        e  = blockIdx.z;
        m0 = blockIdx.x*128;
        n0 = blockIdx.y*NT;
    }

    const int cnt = g_cnt[e];
    if(m0 >= cnt) return;

    if(PHASE==0){
        // wait for this expert's W1/W3 conversion (converters at lower bids)
        const int target = (e==0) ? 256 : 64;
        if(tid==0){
            while(*((volatile int*)&g_done[e]) < target) __nanosleep(256);
        }
        __syncthreads();
        __threadfence();
    }

    extern __shared__ __half sm[];
    __half* sA = sm;              // [3][128][64]
    __half* sW = sm + 3*AST;      // [3][128][64]
    __shared__ int   s_tok[128];
    __shared__ float s_tw [128];

    if(tid < 128){
        int r = min(m0+tid, cnt-1);
        s_tok[tid] = g_tok[e*KT + r];
        if(PHASE==0) s_tw[tid] = g_tw[e*KT + r];
    }
    __syncthreads();

    const __half* Wp0 = (PHASE==0) ? (g_W1 + (size_t)e*KI*KH) : (g_W2 + (size_t)e*KH*KI);
    const __half* Wp1 = g_W3 + (size_t)e*KI*KH;

    auto load_stage = [&](int L){
        const int st = L%3, k0 = L*64;
        uint32_t baseA = smem_u32(sA + st*AST);
        #pragma unroll
        for(int it=0; it<4; it++){
            int c = it*256 + tid;
            int row = c>>3, cb = c&7;
            int sc = cb ^ (row&7);
            const __half* src = (PHASE==0)
                ? (g_X  + (size_t)s_tok[row]*KH + k0 + cb*8)
                : (g_Hb + (size_t)(e*KT + m0 + row)*KI + k0 + cb*8);
            cp16(baseA + row*128 + sc*16, src);
        }
        uint32_t baseW = smem_u32(sW + st*BST);
        #pragma unroll
        for(int it=0; it<4; it++){             // 128 B rows total
            int c = it*256 + tid;
            int row = c>>3, cb = c&7;
            int sc = cb ^ (row&7);
            const __half* W = (PHASE==0 && row>=64) ? Wp1 : Wp0;
            int wrow = (PHASE==0) ? (row&63) : row;
            cp16(baseW + row*128 + sc*16, W + (size_t)(n0+wrow)*KD + k0 + cb*8);
        }
        cp_commit();
    };

    float acc[NB][2][NI][4];
    #pragma unroll
    for(int b=0;b<NB;b++)
        #pragma unroll
        for(int mi=0;mi<2;mi++)
            #pragma unroll
            for(int ni=0;ni<NI;ni++)
                #pragma unroll
                for(int k=0;k<4;k++) acc[b][mi][ni][k]=0.f;

    const int lane = tid & 31, warp = tid >> 5;
    const int wm = (warp>>1)*32, wn = (warp&1)*(NI*8);

    auto compute = [&](int st){
        uint32_t baseA = smem_u32(sA + st*AST);
        uint32_t baseW = smem_u32(sW + st*BST);
        #pragma unroll
        for(int km=0; km<4; km++){
            uint32_t a[2][4];
            #pragma unroll
            for(int mi=0;mi<2;mi++){
                int row = wm + mi*16 + (lane&15);
                int c   = km*2 + (lane>>4);
                int sc  = c ^ (row&7);
                ldsm4(a[mi], baseA + row*128 + sc*16);
            }
            #pragma unroll
            for(int b=0;b<NB;b++){
                uint32_t bw = baseW + b*64*128;
                uint32_t bf[NI][2];
                #pragma unroll
                for(int nb=0;nb<NI/2;nb++){
                    int row = wn + nb*16 + (lane&15);
                    int c   = km*2 + (lane>>4);
                    int sc  = c ^ (row&7);
                    uint32_t r[4];
                    ldsm4(r, bw + row*128 + sc*16);
                    bf[nb*2  ][0]=r[0]; bf[nb*2+1][0]=r[1];
                    bf[nb*2  ][1]=r[2]; bf[nb*2+1][1]=r[3];
                }
                #pragma unroll
                for(int mi=0;mi<2;mi++)
                    #pragma unroll
                    for(int ni=0;ni<NI;ni++)
                        mma16(acc[b][mi][ni], a[mi], bf[ni][0], bf[ni][1]);
            }
        }
    };

    load_stage(0); load_stage(1);
    #pragma unroll 3
    for(int ks=0; ks<KS; ks++){
        if(ks+1<KS) cp_wait<1>(); else cp_wait<0>();
        __syncthreads();
        if(ks+2<KS) load_stage(ks+2);   // overlapped with compute below
        compute(ks%3);
    }

    // epilogue
    #pragma unroll
    for(int mi=0;mi<2;mi++){
        #pragma unroll
        for(int hh=0;hh<2;hh++){
            int row = wm + mi*16 + (lane>>2) + hh*8;
            int r   = m0 + row;
            if(PHASE==0){
                float tw = (r < cnt) ? s_tw[row] : 0.f;
                __half* dst = g_Hb + (size_t)(e*KT + r)*KI + n0;
                #pragma unroll
                for(int ni=0;ni<NI;ni++){
                    int col = wn + ni*8 + (lane&3)*2;
                    float gg0 = acc[0][mi][ni][hh*2], gg1 = acc[0][mi][ni][hh*2+1];
                    float uu0 = acc[NB-1][mi][ni][hh*2], uu1 = acc[NB-1][mi][ni][hh*2+1];
                    float h0 = tw * (gg0/(1.f+__expf(-gg0))) * uu0;
                    float h1 = tw * (gg1/(1.f+__expf(-gg1))) * uu1;
                    *(__half2*)(dst + col) = __floats2half2_rn(h0,h1);
                }
            } else {
                if(r < cnt){
                    int t = s_tok[row];
                    float* dst = out + (size_t)t*KH + n0;
                    #pragma unroll
                    for(int ni=0;ni<NI;ni++){
                        int col = wn + ni*8 + (lane&3)*2;
                        atomicAdd(dst + col    , acc[0][mi][ni][hh*2  ]);
                        atomicAdd(dst + col + 1, acc[0][mi][ni][hh*2+1]);
                    }
                }
            }
        }
    }
}

// ---------- launch ----------
extern "C" void kernel_launch(void* const* d_in, const int* in_sizes, int n_in,
                              void* d_out, int out_size){
    const float* hs = (const float*)d_in[0];
    const float* lg = (const float*)d_in[1];
    const float* w1 = (const float*)d_in[2];
    const float* w2 = (const float*)d_in[3];
    const float* w3 = (const float*)d_in[4];
    float* out = (float*)d_out;

    const int DS = 3*(128*64 + 128*64)*2;  // 98304 B (both phases)
    cudaFuncSetAttribute(k_gemm<0>, cudaFuncAttributeMaxDynamicSharedMemorySize, DS);
    cudaFuncSetAttribute(k_gemm<1>, cudaFuncAttributeMaxDynamicSharedMemorySize, DS);

    k_cvtx <<<2048, 256>>>((const float4*)hs);   // 1 (X cvt + zero g_cnt/g_done)
    k_route<<<KT/256, 256>>>(lg);                // 2

    // 1-D grid: 256 cvt-e0 + 296 gemm-e0 + 448 cvt-e1..7 + rest gemm + 512 w2z
    const int G0 = 256 + 448 + 8*5632 + 512;     // 46272
    k_gemm<0><<<G0, 256, DS>>>(out, (const float4*)w1, (const float4*)w3,
                               (const float4*)w2);                      // 3

    dim3 gB(KT/128, KH/128, KE);  // m fastest
    k_gemm<1><<<gB, 256, DS>>>(out, nullptr, nullptr, nullptr);         // 4
}